// round 14
// baseline (speedup 1.0000x reference)
#include <cuda_runtime.h>
#include <cstdint>
#include <cstddef>

// Problem constants
#define NROWS 32768          // B*T
#define DDIM  256
#define KCODES 1024

// Output layout (float32 concat of reference tuple)
#define Q_OFF    ((size_t)0)
#define LOSS_OFF ((size_t)8388608)
#define IDX_OFF  ((size_t)8388609)
#define CS_OFF   ((size_t)8421377)
#define EMAW_OFF ((size_t)8422401)
#define EMB_OFF  ((size_t)8684545)

#define DECAY 0.99f
#define OMD   ((float)(1.0 - 0.99))
#define EPS   1e-5f
#define KEPS  (1024.0f * 1e-5f)

// Tiling: BM=32 rows/CTA, 128 thr (4 warps), warp = 8 rows x 128 codes,
// thread = 4 rows x 8 codes (acc = 32 float2 = 64 regs) -> 3 CTAs/SM.
#define BM 32
#define NTHR 128
#define ZS 34                      // zsp row stride in float2 (even -> 16B aligned)
#define ZSP_BYTES (128*ZS*8)       // 34816
#define NST 16                     // stages per k-chunk
#define NKC 8
#define NSTOT (NKC*NST)            // 128 total stages
#define NBUF 4                     // cp.async ring depth
#define EST_F4 (4*128)             // float4 per stage buffer (8 KB)
#define EST_BYTES (NBUF*EST_F4*16) // 32768
#define SMEM_BYTES (ZSP_BYTES + EST_BYTES + BM*4 + BM*4 + 4*4)   // 67856

// Scratch (allocation-free rule: __device__ globals)
__device__ __align__(16) float g_e2[KCODES];
__device__ float g_counts[KCODES];
__device__ float g_dw[KCODES * DDIM];
__device__ float g_loss;
__device__ float g_cs[KCODES];

// ---------------------------------------------------------------------------
// packed fp32x2 FMA (PTX-only pattern)
__device__ __forceinline__ void ffma2(float2 &d, float2 a, float2 b) {
    unsigned long long dd = *reinterpret_cast<unsigned long long*>(&d);
    unsigned long long aa = *reinterpret_cast<unsigned long long*>(&a);
    unsigned long long bb = *reinterpret_cast<unsigned long long*>(&b);
    asm("fma.rn.f32x2 %0, %1, %2, %0;" : "+l"(dd) : "l"(aa), "l"(bb));
    d = *reinterpret_cast<float2*>(&dd);
}

__device__ __forceinline__ uint32_t smem_u32(const void* p) {
    uint32_t a;
    asm("{ .reg .u64 t; cvta.to.shared.u64 t, %1; cvt.u32.u64 %0, t; }" : "=r"(a) : "l"(p));
    return a;
}
__device__ __forceinline__ void cp_async16(uint32_t dst, const void* src) {
    asm volatile("cp.async.cg.shared.global [%0], [%1], 16;" :: "r"(dst), "l"(src) : "memory");
}
#define CP_COMMIT()  asm volatile("cp.async.commit_group;" ::: "memory")
#define CP_WAIT2()   asm volatile("cp.async.wait_group 2;" ::: "memory")

// ---------------------------------------------------------------------------
__global__ void vq_init() {
    int i = blockIdx.x * blockDim.x + threadIdx.x;
    if (i < KCODES * DDIM) g_dw[i] = 0.0f;
    if (i < KCODES) g_counts[i] = 0.0f;
    if (i == 0) g_loss = 0.0f;
}

__global__ void vq_nop() {}   // keeps vq_main in the ncu -s5 profiling slot

__global__ void vq_e2(const float* __restrict__ emb) {
    int k = blockIdx.x;
    float v = emb[k * DDIM + threadIdx.x];
    v *= v;
    for (int off = 16; off; off >>= 1) v += __shfl_down_sync(0xffffffffu, v, off);
    __shared__ float red[8];
    int lane = threadIdx.x & 31, wid = threadIdx.x >> 5;
    if (lane == 0) red[wid] = v;
    __syncthreads();
    if (threadIdx.x == 0) {
        float t = 0.f;
        #pragma unroll
        for (int w = 0; w < 8; w++) t += red[w];
        g_e2[k] = t;
    }
}

// ---------------------------------------------------------------------------
// stage S: e chunk (kc = S>>4, st = S&15): 128 codes x 8 d2, code-major float4s
// smem idx = buf*512 + jj*128 + (code ^ ((code>>3)&7))
__device__ __forceinline__ void issue_stage(uint32_t est_u32, const float4* embv,
                                            int S, int tid) {
    int kc = S >> 4, st = S & 15;
    const float4* src = embv + (size_t)(kc * 128 + tid) * 64 + st * 4;
    uint32_t dst = est_u32 + (uint32_t)(((S & (NBUF - 1)) * EST_F4
                                        + (tid ^ ((tid >> 3) & 7))) * 16);
    #pragma unroll
    for (int jj = 0; jj < 4; jj++)
        cp_async16(dst + jj * 128 * 16, src + jj);
}

__global__ __launch_bounds__(NTHR, 3)
void vq_main(const float* __restrict__ z, const float* __restrict__ emb,
             float* __restrict__ outq, float* __restrict__ outidx) {
    extern __shared__ char smem_raw[];
    float2* zsp  = (float2*)smem_raw;                         // z tile, d-pair packed, transposed
    float4* est  = (float4*)(smem_raw + ZSP_BYTES);           // cp.async e ring
    float*  sa   = (float*)(smem_raw + ZSP_BYTES + EST_BYTES);// [BM] ||z_row||^2
    int*    sidx = (int*)(sa + BM);                           // [BM]
    float*  lred = (float*)(sidx + BM);                       // [4]

    const int tid  = threadIdx.x;
    const int lane = tid & 31;
    const int w    = tid >> 5;               // warp -> rows w*8..w*8+7
    const int lr   = lane >> 4;              // 4-row subgroup
    const int lc   = lane & 15;              // 8-code group
    const int slc  = lc & 7;
    const int row0 = blockIdx.x * BM;
    const float4* zv4  = (const float4*)z;
    const float4* embv = (const float4*)emb;
    const uint32_t est_u32 = smem_u32(est);

    // --- load z tile transposed & d-pair packed ---------------------------
    for (int idx = tid; idx < BM * (DDIM / 4); idx += NTHR) {
        int m = idx >> 6;
        int f4 = idx & 63;
        float4 v = zv4[(size_t)(row0 + m) * 64 + f4];
        zsp[(2 * f4) * ZS + m]     = make_float2(v.x, v.y);
        zsp[(2 * f4 + 1) * ZS + m] = make_float2(v.z, v.w);
    }
    // prologue: issue e stages 0..2
    #pragma unroll
    for (int p = 0; p < 3; p++) { issue_stage(est_u32, embv, p, tid); CP_COMMIT(); }
    __syncthreads();

    // ||z||^2 per row (warp-owned 8 rows)
    #pragma unroll
    for (int i = 0; i < 8; i++) {
        int row = w * 8 + i;
        float s = 0.f;
        #pragma unroll
        for (int u = 0; u < 4; u++) {
            float2 p = zsp[(lane + u * 32) * ZS + row];
            s = fmaf(p.x, p.x, fmaf(p.y, p.y, s));
        }
        for (int off = 16; off; off >>= 1) s += __shfl_down_sync(0xffffffffu, s, off);
        if (lane == 0) sa[row] = s;
    }
    __syncthreads();
    float anr[4];
    #pragma unroll
    for (int i = 0; i < 4; i++) anr[i] = sa[w * 8 + lr * 4 + i];

    // --- main loop --------------------------------------------------------
    float bestv[4]; int besti[4];
    #pragma unroll
    for (int i = 0; i < 4; i++) { bestv[i] = 3.402823466e38f; besti[i] = 0; }
    float2 acc[4][8];
    #pragma unroll
    for (int i = 0; i < 4; i++)
        #pragma unroll
        for (int j = 0; j < 8; j++) acc[i][j] = make_float2(0.f, 0.f);

    #pragma unroll 1
    for (int S = 0; S < NSTOT; S++) {
        const int kc = S >> 4, st = S & 15;
        CP_WAIT2();                 // stage S resident
        __syncthreads();            // visible to all; prior buffer reuse safe
        if (S + 3 < NSTOT) issue_stage(est_u32, embv, S + 3, tid);
        CP_COMMIT();                // empty group keeps counts sane

        const float4* ebb = est + (S & (NBUF - 1)) * EST_F4;
        #pragma unroll
        for (int jj = 0; jj < 4; jj++) {
            float4 b4[8];
            #pragma unroll
            for (int j = 0; j < 8; j++)
                b4[j] = ebb[jj * 128 + 8 * lc + (j ^ slc)];
            #pragma unroll
            for (int h = 0; h < 2; h++) {
                // z: 4 rows (float2 each), broadcast across the 16 lc lanes
                const float2* zr = zsp + (st * 8 + jj * 2 + h) * ZS + w * 8 + lr * 4;
                float2 a2[4];
                {
                    float4 t0 = *reinterpret_cast<const float4*>(zr);
                    float4 t1 = *reinterpret_cast<const float4*>(zr + 2);
                    a2[0] = make_float2(t0.x, t0.y); a2[1] = make_float2(t0.z, t0.w);
                    a2[2] = make_float2(t1.x, t1.y); a2[3] = make_float2(t1.z, t1.w);
                }
                #pragma unroll
                for (int i = 0; i < 4; i++)
                    #pragma unroll
                    for (int j = 0; j < 8; j++) {
                        float2 bb = h ? make_float2(b4[j].z, b4[j].w)
                                      : make_float2(b4[j].x, b4[j].y);
                        ffma2(acc[i][j], a2[i], bb);
                    }
            }
        }

        if (st == NST - 1) {
            // scores for this k-chunk, replicating jax rounding:
            // dist = fl( fl(||z||^2 + ||e||^2) - fl(2*dot) )
            float4 e2lo = *reinterpret_cast<const float4*>(&g_e2[kc * 128 + lc * 8]);
            float4 e2hi = *reinterpret_cast<const float4*>(&g_e2[kc * 128 + lc * 8 + 4]);
            float e2a[8] = { e2lo.x, e2lo.y, e2lo.z, e2lo.w,
                             e2hi.x, e2hi.y, e2hi.z, e2hi.w };
            #pragma unroll
            for (int i = 0; i < 4; i++) {
                float an = anr[i];
                #pragma unroll
                for (int j = 0; j < 8; j++) {
                    float dot = acc[i][j].x + acc[i][j].y;
                    float t1 = an + e2a[j];
                    float sc = t1 - 2.0f * dot;
                    int code = kc * 128 + lc * 8 + j;
                    if (sc < bestv[i]) { bestv[i] = sc; besti[i] = code; }
                    acc[i][j] = make_float2(0.f, 0.f);
                }
            }
        }
    }

    // --- argmin reduce across the 16 lc lanes (first-min tie-break) -------
    #pragma unroll
    for (int i = 0; i < 4; i++) {
        float v = bestv[i]; int ix = besti[i];
        #pragma unroll
        for (int off = 8; off; off >>= 1) {
            float ov = __shfl_down_sync(0xffffffffu, v, off, 16);
            int   oi = __shfl_down_sync(0xffffffffu, ix, off, 16);
            if (ov < v || (ov == v && oi < ix)) { v = ov; ix = oi; }
        }
        if (lc == 0) {
            int row = w * 8 + lr * 4 + i;
            sidx[row] = ix;
            outidx[row0 + row] = (float)ix;
        }
    }
    __syncthreads();

    // --- epilogue: quantized gather, loss, counts, dw scatter -------------
    float lsum = 0.f;
    const int d0 = tid * 2;   // 128 threads x 2 floats = DDIM
    for (int r = 0; r < BM; r++) {
        int code = sidx[r];
        size_t go = (size_t)(row0 + r) * DDIM + d0;
        float2 q  = *reinterpret_cast<const float2*>(&emb[(size_t)code * DDIM + d0]);
        float2 zv = *reinterpret_cast<const float2*>(&z[go]);
        *reinterpret_cast<float2*>(&outq[go]) = q;
        float dx = zv.x - q.x, dy = zv.y - q.y;
        lsum = fmaf(dx, dx, fmaf(dy, dy, lsum));
        atomicAdd(&g_dw[code * DDIM + d0], zv.x);
        atomicAdd(&g_dw[code * DDIM + d0 + 1], zv.y);
    }
    if (tid < BM) atomicAdd(&g_counts[sidx[tid]], 1.0f);

    for (int off = 16; off; off >>= 1) lsum += __shfl_down_sync(0xffffffffu, lsum, off);
    if (lane == 0) lred[w] = lsum;
    __syncthreads();
    if (tid == 0) {
        float t = 0.f;
        #pragma unroll
        for (int ww = 0; ww < 4; ww++) t += lred[ww];
        atomicAdd(&g_loss, t);
    }
}

// ---------------------------------------------------------------------------
__global__ void vq_finalize(const float* __restrict__ ema_cs, float* __restrict__ out) {
    int k = threadIdx.x;  // 1024 threads
    float pre = ema_cs[k] * DECAY + OMD * g_counts[k];
    __shared__ float sred[32];
    float v = pre;
    int lane = k & 31, wid = k >> 5;
    for (int off = 16; off; off >>= 1) v += __shfl_down_sync(0xffffffffu, v, off);
    if (lane == 0) sred[wid] = v;
    __syncthreads();
    if (wid == 0) {
        float t = sred[lane];
        for (int off = 16; off; off >>= 1) t += __shfl_down_sync(0xffffffffu, t, off);
        if (lane == 0) sred[0] = t;
    }
    __syncthreads();
    float n = sred[0];
    float cs = (pre + EPS) / (n + KEPS) * n;
    out[CS_OFF + k] = cs;
    g_cs[k] = cs;
    if (k == 0) out[LOSS_OFF] = 0.25f * g_loss / (float)(NROWS * DDIM);
}

__global__ void vq_emaw(const float* __restrict__ ema_w, float* __restrict__ out) {
    int i = blockIdx.x * 256 + threadIdx.x;   // < K*D
    int k = i >> 8;
    float w = ema_w[i] * DECAY + OMD * g_dw[i];
    out[EMAW_OFF + i] = w;
    out[EMB_OFF + i] = w / g_cs[k];
}

// ---------------------------------------------------------------------------
extern "C" void kernel_launch(void* const* d_in, const int* in_sizes, int n_in,
                              void* d_out, int out_size) {
    const float* z      = (const float*)d_in[0];  // [32,1024,256]
    const float* emb    = (const float*)d_in[1];  // [1024,256]
    const float* ema_cs = (const float*)d_in[2];  // [1024]
    const float* ema_w  = (const float*)d_in[3];  // [1024,256]
    float* out = (float*)d_out;
    (void)in_sizes; (void)n_in; (void)out_size;

    cudaFuncSetAttribute(vq_main, cudaFuncAttributeMaxDynamicSharedMemorySize, SMEM_BYTES);

    vq_init<<<(KCODES * DDIM + 255) / 256, 256>>>();            // 1
    vq_e2<<<KCODES, 256>>>(emb);                                // 2
    vq_nop<<<1, 32>>>();                                        // 3
    vq_main<<<NROWS / BM, NTHR, SMEM_BYTES>>>(z, emb, out + Q_OFF, out + IDX_OFF);  // 4
    vq_finalize<<<1, 1024>>>(ema_cs, out);                      // 5
    vq_emaw<<<KCODES * DDIM / 256, 256>>>(ema_w, out);          // 6
}

// round 16
// speedup vs baseline: 1.4469x; 1.4469x over previous
#include <cuda_runtime.h>
#include <cuda_fp16.h>
#include <cstdint>
#include <cstddef>

// Problem constants
#define NROWS 32768          // B*T
#define DDIM  256
#define KCODES 1024

// Output layout (float32 concat of reference tuple)
#define Q_OFF    ((size_t)0)
#define LOSS_OFF ((size_t)8388608)
#define IDX_OFF  ((size_t)8388609)
#define CS_OFF   ((size_t)8421377)
#define EMAW_OFF ((size_t)8422401)
#define EMB_OFF  ((size_t)8684545)

#define DECAY 0.99f
#define OMD   ((float)(1.0 - 0.99))
#define EPS   1e-5f
#define KEPS  (1024.0f * 1e-5f)

// vq_main tiling: BM=64 rows/CTA, 128 thr (4 warps), warp = 16 rows x 128 codes,
// thread = 8 rows x 8 codes, int32 accumulators, D=256 int8 dims.
#define BM 64
#define NTHR 128
#define ZROWB 272                        // padded int8 z row stride (17*16)
#define Z8_BYTES (BM*ZROWB)              // 17408
#define ECH_BYTES 32768                  // one e chunk: 128 codes x 256 int8
#define SMEM_BYTES (Z8_BYTES + 2*ECH_BYTES)   // 82944

// Scratch (allocation-free rule: __device__ globals)
__device__ __align__(16) float g_e2[KCODES];
__device__ __align__(16) float g_zn[NROWS];
__device__ __align__(16) float g_sza[NROWS];
__device__ float g_counts[KCODES];
__device__ float g_dw[KCODES * DDIM];
__device__ float g_loss;
__device__ float g_cs[KCODES];
__device__ unsigned g_maxz_u, g_maxe_u, g_saemax_u;
__device__ __align__(16) unsigned char g_zq[(size_t)NROWS * DDIM];   // 8 MB int8 z
__device__ __align__(16) unsigned char g_eq[KCODES * DDIM];          // 256 KB int8 e
__device__ __align__(16) __half g_sc[(size_t)NROWS * KCODES];        // 64 MB delta-scores

// ---------------------------------------------------------------------------
__device__ __forceinline__ uint32_t smem_u32(const void* p) {
    uint32_t a;
    asm("{ .reg .u64 t; cvta.to.shared.u64 t, %1; cvt.u32.u64 %0, t; }" : "=r"(a) : "l"(p));
    return a;
}
__device__ __forceinline__ void cp_async16(uint32_t dst, const void* src) {
    asm volatile("cp.async.cg.shared.global [%0], [%1], 16;" :: "r"(dst), "l"(src) : "memory");
}
#define CP_COMMIT()  asm volatile("cp.async.commit_group;" ::: "memory")
#define CP_WAIT1()   asm volatile("cp.async.wait_group 1;" ::: "memory")
#define CP_WAIT0()   asm volatile("cp.async.wait_group 0;" ::: "memory")

__device__ __forceinline__ unsigned pack4(int q0, int q1, int q2, int q3) {
    return (unsigned)(q0 & 0xff) | ((unsigned)(q1 & 0xff) << 8) |
           ((unsigned)(q2 & 0xff) << 16) | ((unsigned)(q3 & 0xff) << 24);
}
__device__ __forceinline__ int q8(float x, float inv) {
    int q = __float2int_rn(x * inv);
    return max(-127, min(127, q));
}

// ======================= prep kernels ======================================
__global__ void vq_init() {
    int i = blockIdx.x * blockDim.x + threadIdx.x;
    if (i < KCODES * DDIM) g_dw[i] = 0.0f;
    if (i < KCODES) g_counts[i] = 0.0f;
    if (i == 0) { g_loss = 0.0f; g_maxz_u = 0u; g_maxe_u = 0u; g_saemax_u = 0u; }
}

__global__ void vq_e2(const float* __restrict__ emb) {
    int k = blockIdx.x;
    float v = emb[k * DDIM + threadIdx.x];
    float s2v = v * v;
    float av = fabsf(v), sav = av, mav = av;
    for (int off = 16; off; off >>= 1) {
        s2v += __shfl_down_sync(0xffffffffu, s2v, off);
        sav += __shfl_down_sync(0xffffffffu, sav, off);
        mav = fmaxf(mav, __shfl_down_sync(0xffffffffu, mav, off));
    }
    __shared__ float r2[8], ra[8], rm[8];
    int lane = threadIdx.x & 31, wid = threadIdx.x >> 5;
    if (lane == 0) { r2[wid] = s2v; ra[wid] = sav; rm[wid] = mav; }
    __syncthreads();
    if (threadIdx.x == 0) {
        float t = 0.f, ta = 0.f, tm = 0.f;
        #pragma unroll
        for (int w = 0; w < 8; w++) { t += r2[w]; ta += ra[w]; tm = fmaxf(tm, rm[w]); }
        g_e2[k] = t;
        atomicMax(&g_saemax_u, __float_as_uint(ta * 1.001f + 1e-7f));
        atomicMax(&g_maxe_u, __float_as_uint(tm));
    }
}

__global__ void vq_zn(const float* __restrict__ z) {
    int r = blockIdx.x * 128 + threadIdx.x;
    const float4* p = (const float4*)(z + (size_t)r * DDIM);
    float s = 0.f, sa = 0.f, mx = 0.f;
    #pragma unroll
    for (int i = 0; i < 64; i++) {
        float4 v = p[i];
        s = fmaf(v.x, v.x, s); s = fmaf(v.y, v.y, s);
        s = fmaf(v.z, v.z, s); s = fmaf(v.w, v.w, s);
        sa += fabsf(v.x) + fabsf(v.y) + fabsf(v.z) + fabsf(v.w);
        mx = fmaxf(mx, fmaxf(fmaxf(fabsf(v.x), fabsf(v.y)), fmaxf(fabsf(v.z), fabsf(v.w))));
    }
    g_zn[r] = s;
    g_sza[r] = sa * 1.001f + 1e-7f;
    for (int off = 16; off; off >>= 1) mx = fmaxf(mx, __shfl_down_sync(0xffffffffu, mx, off));
    if ((threadIdx.x & 31) == 0) atomicMax(&g_maxz_u, __float_as_uint(mx));
}

__global__ void vq_qz(const float* __restrict__ z) {
    int t = blockIdx.x * 256 + threadIdx.x;          // handles 8 floats
    float maxz = fmaxf(__uint_as_float(g_maxz_u), 1e-30f);
    float inv = 127.0f / maxz;
    const float4* zp = ((const float4*)z) + (size_t)t * 2;
    float4 a = zp[0], b = zp[1];
    uint2 o;
    o.x = pack4(q8(a.x, inv), q8(a.y, inv), q8(a.z, inv), q8(a.w, inv));
    o.y = pack4(q8(b.x, inv), q8(b.y, inv), q8(b.z, inv), q8(b.w, inv));
    ((uint2*)g_zq)[t] = o;
}

__global__ void vq_qe(const float* __restrict__ emb) {
    int t = blockIdx.x * 256 + threadIdx.x;          // handles 8 floats
    float maxe = fmaxf(__uint_as_float(g_maxe_u), 1e-30f);
    float inv = 127.0f / maxe;
    const float4* ep = ((const float4*)emb) + (size_t)t * 2;
    float4 a = ep[0], b = ep[1];
    uint2 o;
    o.x = pack4(q8(a.x, inv), q8(a.y, inv), q8(a.z, inv), q8(a.w, inv));
    o.y = pack4(q8(b.x, inv), q8(b.y, inv), q8(b.z, inv), q8(b.w, inv));
    ((uint2*)g_eq)[t] = o;
}

// ======================= main kernel =======================================
// e chunk stage layout: [kg 0..15][128 codes swizzled][16B], code c at
// phys(c) = 8*(c>>3) + ((c&7) ^ ((c>>3)&7)).
__device__ __forceinline__ void issue_e(uint32_t eru, int ch, int tid) {
    const unsigned char* src = g_eq + (size_t)(ch * 128 + tid) * 256;
    int phys = 8 * (tid >> 3) + ((tid & 7) ^ ((tid >> 3) & 7));
    uint32_t dst = eru + (uint32_t)((ch & 1) * ECH_BYTES + phys * 16);
    #pragma unroll
    for (int kg = 0; kg < 16; kg++)
        cp_async16(dst + kg * 2048, src + kg * 16);
}

__global__ __launch_bounds__(NTHR, 2)
void vq_main(const float* __restrict__ z, const float* __restrict__ emb,
             float* __restrict__ out) {
    extern __shared__ char smem[];
    char* z8 = smem;
    char* er = smem + Z8_BYTES;
    const int tid  = threadIdx.x;
    const int lane = tid & 31;
    const int w    = tid >> 5;
    const int lr   = lane >> 4;
    const int lc   = lane & 15;
    const int slc  = lc & 7;
    const int row0 = blockIdx.x * BM;
    const uint32_t z8u = smem_u32(z8), eru = smem_u32(er);

    // scales (deterministic, same on all threads)
    const float maxz = fmaxf(__uint_as_float(g_maxz_u), 1e-30f);
    const float maxe = fmaxf(__uint_as_float(g_maxe_u), 1e-30f);
    const float invz = 127.0f / maxz, inve = 127.0f / maxe;
    const float szz = 1.0f / invz, sze = 1.0f / inve;
    const float m2s2 = -2.0f * (szz * sze);

    // cp.async z tile (64 rows x 256 int8, padded rows)
    for (int n = tid; n < BM * 16; n += NTHR) {
        int row = n >> 4, kg = n & 15;
        cp_async16(z8u + (uint32_t)(row * ZROWB + kg * 16),
                   g_zq + (size_t)(row0 + row) * 256 + kg * 16);
    }
    CP_COMMIT();
    issue_e(eru, 0, tid); CP_COMMIT();
    issue_e(eru, 1, tid); CP_COMMIT();

    // precomputed offsets
    int aoff[8], boff[8];
    #pragma unroll
    for (int i = 0; i < 8; i++) aoff[i] = (w * 16 + lr * 8 + i) * ZROWB;
    #pragma unroll
    for (int j = 0; j < 8; j++) boff[j] = (8 * lc + (j ^ slc)) * 16;

    // ---- phase 1: dp4a score GEMM, fp16 delta-scores to global ----------
    #pragma unroll 1
    for (int c = 0; c < 8; c++) {
        if (c == 7) { CP_WAIT0(); } else { CP_WAIT1(); }
        __syncthreads();
        const char* eb = er + (c & 1) * ECH_BYTES;

        int acc[8][8];
        #pragma unroll
        for (int i = 0; i < 8; i++)
            #pragma unroll
            for (int j = 0; j < 8; j++) acc[i][j] = 0;

        #pragma unroll 2
        for (int kg = 0; kg < 16; kg++) {
            uint4 au[8], bu[8];
            #pragma unroll
            for (int i = 0; i < 8; i++)
                au[i] = *(const uint4*)(z8 + aoff[i] + kg * 16);
            #pragma unroll
            for (int j = 0; j < 8; j++)
                bu[j] = *(const uint4*)(eb + kg * 2048 + boff[j]);
            #pragma unroll
            for (int i = 0; i < 8; i++)
                #pragma unroll
                for (int j = 0; j < 8; j++) {
                    acc[i][j] = __dp4a((int)au[i].x, (int)bu[j].x, acc[i][j]);
                    acc[i][j] = __dp4a((int)au[i].y, (int)bu[j].y, acc[i][j]);
                    acc[i][j] = __dp4a((int)au[i].z, (int)bu[j].z, acc[i][j]);
                    acc[i][j] = __dp4a((int)au[i].w, (int)bu[j].w, acc[i][j]);
                }
        }

        // delta-scores A = e2 - 2*s2*dotq (fp16-rounded), store
        float4 e2a = *(const float4*)(g_e2 + c * 128 + lc * 8);
        float4 e2b = *(const float4*)(g_e2 + c * 128 + lc * 8 + 4);
        float e2v[8] = { e2a.x, e2a.y, e2a.z, e2a.w, e2b.x, e2b.y, e2b.z, e2b.w };
        #pragma unroll
        for (int i = 0; i < 8; i++) {
            int grow = row0 + w * 16 + lr * 8 + i;
            float s[8];
            #pragma unroll
            for (int j = 0; j < 8; j++)
                s[j] = fmaf(__int2float_rn(acc[i][j]), m2s2, e2v[j]);
            uint4 pk;
            __half2* ph = (__half2*)&pk;
            ph[0] = __floats2half2_rn(s[0], s[1]);
            ph[1] = __floats2half2_rn(s[2], s[3]);
            ph[2] = __floats2half2_rn(s[4], s[5]);
            ph[3] = __floats2half2_rn(s[6], s[7]);
            *(uint4*)(g_sc + (size_t)grow * 1024 + c * 128 + lc * 8) = pk;
        }
        __syncthreads();
        if (c + 2 < 8) issue_e(eru, c + 2, tid);
        CP_COMMIT();
    }
    __syncthreads();   // global score visibility within block

    // ---- phase 2: per-row scan -> thr -> candidates -> exact rescore -----
    const float saemax = __uint_as_float(g_saemax_u);
    const float de = 0.5004f * sze;
    const float dz = 0.5004f * szz;
    const float mbase = 2.1f * (dz * saemax + 256.0f * dz * de) + 6e-4f;

    #pragma unroll 1
    for (int rr = 0; rr < 16; rr++) {
        const int grow = row0 + w * 16 + rr;
        const uint4* sp = (const uint4*)(g_sc + (size_t)grow * 1024);
        uint4 sv[4];
        float smin = 3.402823466e38f; int simin = 0;
        #pragma unroll
        for (int q = 0; q < 4; q++) {
            sv[q] = sp[q * 32 + lane];
            const __half2* hh = (const __half2*)&sv[q];
            float2 f0 = __half22float2(hh[0]);
            float2 f1 = __half22float2(hh[1]);
            float2 f2 = __half22float2(hh[2]);
            float2 f3 = __half22float2(hh[3]);
            float fs[8] = { f0.x, f0.y, f1.x, f1.y, f2.x, f2.y, f3.x, f3.y };
            #pragma unroll
            for (int k = 0; k < 8; k++) {
                int code = q * 256 + lane * 8 + k;
                if (fs[k] < smin) { smin = fs[k]; simin = code; }
            }
        }
        for (int off = 16; off; off >>= 1) {
            float ov = __shfl_down_sync(0xffffffffu, smin, off);
            int   oi = __shfl_down_sync(0xffffffffu, simin, off);
            if (ov < smin || (ov == smin && oi < simin)) { smin = ov; simin = oi; }
        }
        const float thr = __shfl_sync(0xffffffffu, smin, 0)
                        + fmaf(2.1f * de, g_sza[grow], mbase);

        const float4* zp = (const float4*)(z + (size_t)grow * DDIM);
        const float4 z0 = zp[lane * 2], z1 = zp[lane * 2 + 1];
        const float zn = g_zn[grow];

        float bestsc = 3.402823466e38f; int bestidx = 0x7fffffff;
        #pragma unroll 1
        for (int q = 0; q < 4; q++) {
            const __half2* hh = (const __half2*)&sv[q];
            float2 f0 = __half22float2(hh[0]);
            float2 f1 = __half22float2(hh[1]);
            float2 f2 = __half22float2(hh[2]);
            float2 f3 = __half22float2(hh[3]);
            float fs[8] = { f0.x, f0.y, f1.x, f1.y, f2.x, f2.y, f3.x, f3.y };
            #pragma unroll 1
            for (int k = 0; k < 8; k++) {
                unsigned m = __ballot_sync(0xffffffffu, fs[k] <= thr);
                while (m) {
                    int src = __ffs(m) - 1; m &= m - 1;
                    int cc = q * 256 + src * 8 + k;
                    const float4* ep = (const float4*)(emb + (size_t)cc * DDIM);
                    float4 e0 = ep[lane * 2], e1 = ep[lane * 2 + 1];
                    float p = 0.f;
                    p = fmaf(z0.x, e0.x, p); p = fmaf(z0.y, e0.y, p);
                    p = fmaf(z0.z, e0.z, p); p = fmaf(z0.w, e0.w, p);
                    p = fmaf(z1.x, e1.x, p); p = fmaf(z1.y, e1.y, p);
                    p = fmaf(z1.z, e1.z, p); p = fmaf(z1.w, e1.w, p);
                    for (int o = 16; o; o >>= 1) p += __shfl_xor_sync(0xffffffffu, p, o);
                    // exact reference rounding: fl( fl(zn+e2) - fl(2*dot) )
                    float sce = __fsub_rn(__fadd_rn(zn, g_e2[cc]), __fmul_rn(2.f, p));
                    if (sce < bestsc || (sce == bestsc && cc < bestidx)) { bestsc = sce; bestidx = cc; }
                }
            }
        }
        const int code = bestidx;

        // fused row epilogue (proven)
        const float4* qp = (const float4*)(emb + (size_t)code * DDIM);
        float4 q0 = qp[lane * 2], q1 = qp[lane * 2 + 1];
        float4* oq = (float4*)(out + Q_OFF + (size_t)grow * DDIM);
        oq[lane * 2] = q0; oq[lane * 2 + 1] = q1;
        float ls = 0.f;
        {
            float d;
            d = z0.x - q0.x; ls = fmaf(d, d, ls);
            d = z0.y - q0.y; ls = fmaf(d, d, ls);
            d = z0.z - q0.z; ls = fmaf(d, d, ls);
            d = z0.w - q0.w; ls = fmaf(d, d, ls);
            d = z1.x - q1.x; ls = fmaf(d, d, ls);
            d = z1.y - q1.y; ls = fmaf(d, d, ls);
            d = z1.z - q1.z; ls = fmaf(d, d, ls);
            d = z1.w - q1.w; ls = fmaf(d, d, ls);
        }
        for (int o = 16; o; o >>= 1) ls += __shfl_xor_sync(0xffffffffu, ls, o);
        int base = code * DDIM + lane * 8;
        atomicAdd(&g_dw[base + 0], z0.x); atomicAdd(&g_dw[base + 1], z0.y);
        atomicAdd(&g_dw[base + 2], z0.z); atomicAdd(&g_dw[base + 3], z0.w);
        atomicAdd(&g_dw[base + 4], z1.x); atomicAdd(&g_dw[base + 5], z1.y);
        atomicAdd(&g_dw[base + 6], z1.z); atomicAdd(&g_dw[base + 7], z1.w);
        if (lane == 0) {
            out[IDX_OFF + grow] = (float)code;
            atomicAdd(&g_counts[code], 1.0f);
            atomicAdd(&g_loss, ls);
        }
    }
}

// ======================= EMA finalize kernels ==============================
__global__ void vq_finalize(const float* __restrict__ ema_cs, float* __restrict__ out) {
    int k = threadIdx.x;  // 1024 threads
    float pre = ema_cs[k] * DECAY + OMD * g_counts[k];
    __shared__ float sred[32];
    float v = pre;
    int lane = k & 31, wid = k >> 5;
    for (int off = 16; off; off >>= 1) v += __shfl_down_sync(0xffffffffu, v, off);
    if (lane == 0) sred[wid] = v;
    __syncthreads();
    if (wid == 0) {
        float t = sred[lane];
        for (int off = 16; off; off >>= 1) t += __shfl_down_sync(0xffffffffu, t, off);
        if (lane == 0) sred[0] = t;
    }
    __syncthreads();
    float n = sred[0];
    float cs = (pre + EPS) / (n + KEPS) * n;
    out[CS_OFF + k] = cs;
    g_cs[k] = cs;
    if (k == 0) out[LOSS_OFF] = 0.25f * g_loss / (float)(NROWS * DDIM);
}

__global__ void vq_emaw(const float* __restrict__ ema_w, float* __restrict__ out) {
    int i = blockIdx.x * 256 + threadIdx.x;   // < K*D
    int k = i >> 8;
    float w = ema_w[i] * DECAY + OMD * g_dw[i];
    out[EMAW_OFF + i] = w;
    out[EMB_OFF + i] = w / g_cs[k];
}

// ---------------------------------------------------------------------------
extern "C" void kernel_launch(void* const* d_in, const int* in_sizes, int n_in,
                              void* d_out, int out_size) {
    const float* z      = (const float*)d_in[0];  // [32,1024,256]
    const float* emb    = (const float*)d_in[1];  // [1024,256]
    const float* ema_cs = (const float*)d_in[2];  // [1024]
    const float* ema_w  = (const float*)d_in[3];  // [1024,256]
    float* out = (float*)d_out;
    (void)in_sizes; (void)n_in; (void)out_size;

    cudaFuncSetAttribute(vq_main, cudaFuncAttributeMaxDynamicSharedMemorySize, SMEM_BYTES);

    vq_init<<<(KCODES * DDIM + 255) / 256, 256>>>();              // 1
    vq_e2<<<KCODES, 256>>>(emb);                                  // 2
    vq_zn<<<NROWS / 128, 128>>>(z);                               // 3
    vq_qz<<<NROWS * DDIM / 8 / 256, 256>>>(z);                    // 4
    vq_qe<<<KCODES * DDIM / 8 / 256, 256>>>(emb);                 // 5
    vq_main<<<NROWS / BM, NTHR, SMEM_BYTES>>>(z, emb, out);       // 6 <- ncu slot
    vq_finalize<<<1, 1024>>>(ema_cs, out);                        // 7
    vq_emaw<<<KCODES * DDIM / 256, 256>>>(ema_w, out);            // 8
}